// round 5
// baseline (speedup 1.0000x reference)
#include <cuda_runtime.h>

#define N_NODES 100000
#define N_EDGES 1600000
#define NH 8
#define ND 16
#define HD 128
#define G_GRAPHS 128
#define OUT_DIM 64
#define BN_EPS 1e-3f
#define NEG_SLOPE 0.2f

// ---------------- device scratch (no allocations allowed) ----------------
__device__ float g_feat[N_NODES * HD];    // W-transformed features (per layer, reused)
__device__ float g_agg[N_NODES * HD];     // GAT aggregation output (reused)
__device__ float g_h1[N_NODES * HD];      // layer-0 output (residual input)
__device__ float g_ee[N_EDGES * NH];      // exp(leaky_relu(el+er)) per edge/head
__device__ float g_el[N_NODES * NH];
__device__ float g_er[N_NODES * NH];
__device__ float g_denom[N_NODES * NH];   // softmax denominators
__device__ float g_bnsum[HD];
__device__ float g_bnsum2[HD];
__device__ float g_scale[HD];
__device__ float g_shift[HD];
__device__ float g_pooled[G_GRAPHS * HD];

// Vectorized global float4 reduction (sm_90+)
__device__ __forceinline__ void red_add_v4(float* addr, float4 v) {
    asm volatile("red.global.add.v4.f32 [%0], {%1,%2,%3,%4};"
                 :: "l"(addr), "f"(v.x), "f"(v.y), "f"(v.z), "f"(v.w)
                 : "memory");
}

// ---------------- zero scratch ----------------
__global__ void zero_scratch(int zero_pooled) {
    int i = blockIdx.x * blockDim.x + threadIdx.x;
    float4 z = make_float4(0.f, 0.f, 0.f, 0.f);
    if (i < N_NODES * HD / 4) ((float4*)g_agg)[i] = z;
    if (i < N_NODES * NH / 4) ((float4*)g_denom)[i] = z;
    if (i < HD / 4) {
        ((float4*)g_bnsum)[i] = z;
        ((float4*)g_bnsum2)[i] = z;
    }
    if (zero_pooled && i < G_GRAPHS * HD / 4) ((float4*)g_pooled)[i] = z;
}

// ---------------- GEMM: feat = A @ W, A:[N,128] W:[128,128] ----------------
// 64-row x 128-col tile per block, 256 threads, each thread 8x4 outputs.
__global__ void __launch_bounds__(256) gemm128(const float* __restrict__ Aext,
                                               const float* __restrict__ W,
                                               int use_h1) {
    const float* A = use_h1 ? g_h1 : Aext;
    __shared__ float As[64][33];
    __shared__ float Ws[32][128];
    int t = threadIdx.x;
    int r0 = blockIdx.x * 64;
    int cg = (t & 31) * 4;   // column base (0..124)
    int rg = (t >> 5) * 8;   // row base within tile (0..56)

    float acc[8][4];
#pragma unroll
    for (int i = 0; i < 8; i++)
#pragma unroll
        for (int j = 0; j < 4; j++) acc[i][j] = 0.f;

    for (int kc = 0; kc < HD; kc += 32) {
        // load A tile 64x32
        for (int i = t; i < 64 * 32; i += 256) {
            int r = i >> 5, k = i & 31;
            int row = r0 + r;
            As[r][k] = (row < N_NODES) ? A[row * HD + kc + k] : 0.f;
        }
        // load W tile 32x128
        for (int i = t; i < 32 * 128; i += 256) {
            int k = i >> 7, c = i & 127;
            Ws[k][c] = W[(kc + k) * HD + c];
        }
        __syncthreads();
#pragma unroll
        for (int k = 0; k < 32; k++) {
            float4 wv = *(const float4*)&Ws[k][cg];
#pragma unroll
            for (int i = 0; i < 8; i++) {
                float av = As[rg + i][k];
                acc[i][0] += av * wv.x;
                acc[i][1] += av * wv.y;
                acc[i][2] += av * wv.z;
                acc[i][3] += av * wv.w;
            }
        }
        __syncthreads();
    }
#pragma unroll
    for (int i = 0; i < 8; i++) {
        int row = r0 + rg + i;
        if (row < N_NODES) {
            *(float4*)&g_feat[row * HD + cg] =
                make_float4(acc[i][0], acc[i][1], acc[i][2], acc[i][3]);
        }
    }
}

// ---------------- per-node attention halves: el/er ----------------
__global__ void compute_elr(const float* __restrict__ al, const float* __restrict__ ar) {
    int idx = blockIdx.x * blockDim.x + threadIdx.x;  // (node, head)
    if (idx >= N_NODES * NH) return;
    int h = idx & (NH - 1);
    const float4* f4 = (const float4*)&g_feat[idx * ND];
    const float4* a4 = (const float4*)&al[h * ND];
    const float4* b4 = (const float4*)&ar[h * ND];
    float el = 0.f, er = 0.f;
#pragma unroll
    for (int j = 0; j < 4; j++) {
        float4 f = f4[j];
        float4 a = a4[j];
        float4 b = b4[j];
        el += f.x * a.x + f.y * a.y + f.z * a.z + f.w * a.w;
        er += f.x * b.x + f.y * b.y + f.z * b.z + f.w * b.w;
    }
    g_el[idx] = el;
    g_er[idx] = er;
}

__device__ __forceinline__ float expleaky(float x) {
    x = (x > 0.f) ? x : NEG_SLOPE * x;
    return __expf(x);
}

// ---------------- edge pass 1: numerators + denominators ----------------
// exp(e - emax) / sum == exp(e) / sum(exp(e)); e is O(±4) so no max needed.
__global__ void edge_softmax_num(const int* __restrict__ src, const int* __restrict__ dst) {
    int e = blockIdx.x * blockDim.x + threadIdx.x;
    if (e >= N_EDGES) return;
    int s = src[e], d = dst[e];
    const float4* l4 = (const float4*)&g_el[s * NH];
    const float4* r4 = (const float4*)&g_er[d * NH];
#pragma unroll
    for (int j = 0; j < 2; j++) {
        float4 l = l4[j];
        float4 r = r4[j];
        float4 o;
        o.x = expleaky(l.x + r.x);
        o.y = expleaky(l.y + r.y);
        o.z = expleaky(l.z + r.z);
        o.w = expleaky(l.w + r.w);
        ((float4*)&g_ee[e * NH])[j] = o;
        red_add_v4(&g_denom[d * NH + j * 4], o);
    }
}

// ---------------- edge pass 2: normalize + scatter messages ----------------
// One warp per edge. lane -> (head = lane>>2, 4 channels = lane*4..lane*4+3).
__global__ void edge_scatter(const int* __restrict__ src, const int* __restrict__ dst) {
    int gt = blockIdx.x * blockDim.x + threadIdx.x;
    int gw = gt >> 5;
    int lane = threadIdx.x & 31;
    if (gw >= N_EDGES) return;
    int s = src[gw], d = dst[gw];
    int h = lane >> 2;
    float num = g_ee[gw * NH + h];
    float den = g_denom[d * NH + h];
    float a = __fdividef(num, den);
    float4 f = ((const float4*)&g_feat[s * HD])[lane];
    red_add_v4(&g_agg[d * HD + lane * 4],
               make_float4(a * f.x, a * f.y, a * f.z, a * f.w));
}

// ---------------- BatchNorm statistics ----------------
#define BN_ROWS 512
__global__ void bn_stats() {
    int c = threadIdx.x;  // 128 channels
    int r0 = blockIdx.x * BN_ROWS;
    int r1 = min(r0 + BN_ROWS, N_NODES);
    float s = 0.f, s2 = 0.f;
    for (int r = r0; r < r1; r++) {
        float x = g_agg[r * HD + c];
        s += x;
        s2 += x * x;
    }
    atomicAdd(&g_bnsum[c], s);
    atomicAdd(&g_bnsum2[c], s2);
}

// Note: GAT bias b cancels inside BN (x - mean(x)), so it is never applied.
__global__ void bn_finalize(const float* __restrict__ gm, const float* __restrict__ be) {
    int c = threadIdx.x;
    float inv_n = 1.0f / (float)N_NODES;
    float mu = g_bnsum[c] * inv_n;
    float var = g_bnsum2[c] * inv_n - mu * mu;
    float rs = rsqrtf(var + BN_EPS);
    float sc = rs * gm[c];
    g_scale[c] = sc;
    g_shift[c] = be[c] - mu * sc;
}

// ---------------- layer 0 epilogue: h1 = relu(bn(agg)) ----------------
__global__ void apply_bn_relu() {
    int i = blockIdx.x * blockDim.x + threadIdx.x;  // per float4
    if (i >= N_NODES * HD / 4) return;
    int c4 = i & 31;
    float4 x = ((const float4*)g_agg)[i];
    float4 sc = ((const float4*)g_scale)[c4];
    float4 sh = ((const float4*)g_shift)[c4];
    x.x = fmaxf(x.x * sc.x + sh.x, 0.f);
    x.y = fmaxf(x.y * sc.y + sh.y, 0.f);
    x.z = fmaxf(x.z * sc.z + sh.z, 0.f);
    x.w = fmaxf(x.w * sc.w + sh.w, 0.f);
    ((float4*)g_h1)[i] = x;
}

// ---------------- layer 1 epilogue fused with sum-pool ----------------
// h2 = relu(bn(agg)) + h1; pooled[gid] += h2. graph_ids are sorted, so we
// run-length accumulate in registers and emit few atomics.
#define POOL_ROWS 512
__global__ void apply_bn_relu_res_pool(const int* __restrict__ gid) {
    int c = threadIdx.x;  // 128 channels
    int r0 = blockIdx.x * POOL_ROWS;
    int r1 = min(r0 + POOL_ROWS, N_NODES);
    float sc = g_scale[c], sh = g_shift[c];
    float acc = 0.f;
    int cur = gid[r0];
    for (int r = r0; r < r1; r++) {
        int g = gid[r];
        float x = g_agg[r * HD + c] * sc + sh;
        x = fmaxf(x, 0.f) + g_h1[r * HD + c];
        if (g != cur) {
            atomicAdd(&g_pooled[cur * HD + c], acc);
            acc = 0.f;
            cur = g;
        }
        acc += x;
    }
    atomicAdd(&g_pooled[cur * HD + c], acc);
}

// ---------------- masked prediction head ----------------
__global__ void final_linear(const float* __restrict__ pW, const float* __restrict__ pb,
                             const float* __restrict__ mask, float* __restrict__ out) {
    __shared__ float p[HD];
    int g = blockIdx.x;
    int o = threadIdx.x;  // 64 threads
    p[o] = g_pooled[g * HD + o];
    p[o + 64] = g_pooled[g * HD + o + 64];
    __syncthreads();
    float s = 0.f;
#pragma unroll 4
    for (int c = 0; c < HD; c++) {
        float w = pW[o * HD + c];
        float m = (mask[o * HD + c] > 0.5f) ? 1.f : 0.f;
        s += p[c] * w * m;
    }
    out[g * OUT_DIM + o] = s + pb[o];
}

// ---------------- launch ----------------
extern "C" void kernel_launch(void* const* d_in, const int* in_sizes, int n_in,
                              void* d_out, int out_size) {
    const float* h    = (const float*)d_in[0];
    const int*   src  = (const int*)d_in[1];
    const int*   dst  = (const int*)d_in[2];
    const int*   gid  = (const int*)d_in[3];
    const float* W0   = (const float*)d_in[4];
    const float* al0  = (const float*)d_in[5];
    const float* ar0  = (const float*)d_in[6];
    // d_in[7] = b0 (cancels in BN)
    const float* g0   = (const float*)d_in[8];
    const float* be0  = (const float*)d_in[9];
    const float* W1   = (const float*)d_in[10];
    const float* al1  = (const float*)d_in[11];
    const float* ar1  = (const float*)d_in[12];
    // d_in[13] = b1 (cancels in BN)
    const float* g1   = (const float*)d_in[14];
    const float* be1  = (const float*)d_in[15];
    const float* pW   = (const float*)d_in[16];
    const float* pb   = (const float*)d_in[17];
    const float* mask = (const float*)d_in[18];
    float* out = (float*)d_out;

    const int zgrid   = (N_NODES * HD / 4 + 255) / 256;          // 12500
    const int ggrid   = (N_NODES + 63) / 64;                     // 1563
    const int elrgrid = (N_NODES * NH + 255) / 256;              // 3125
    const int egrid   = (N_EDGES + 255) / 256;                   // 6250
    const int sgrid   = (N_EDGES * 32) / 256;                    // 200000
    const int agrid   = (N_NODES * HD / 4 + 255) / 256;          // 12500
    const int bngrid  = (N_NODES + BN_ROWS - 1) / BN_ROWS;       // 196

    // ---- layer 0 ----
    zero_scratch<<<zgrid, 256>>>(1);
    gemm128<<<ggrid, 256>>>(h, W0, 0);
    compute_elr<<<elrgrid, 256>>>(al0, ar0);
    edge_softmax_num<<<egrid, 256>>>(src, dst);
    edge_scatter<<<sgrid, 256>>>(src, dst);
    bn_stats<<<bngrid, 128>>>();
    bn_finalize<<<1, 128>>>(g0, be0);
    apply_bn_relu<<<agrid, 256>>>();

    // ---- layer 1 ----
    zero_scratch<<<zgrid, 256>>>(0);
    gemm128<<<ggrid, 256>>>(nullptr, W1, 1);
    compute_elr<<<elrgrid, 256>>>(al1, ar1);
    edge_softmax_num<<<egrid, 256>>>(src, dst);
    edge_scatter<<<sgrid, 256>>>(src, dst);
    bn_stats<<<bngrid, 128>>>();
    bn_finalize<<<1, 128>>>(g1, be1);
    apply_bn_relu_res_pool<<<bngrid, 128>>>(gid);

    // ---- head ----
    final_linear<<<G_GRAPHS, OUT_DIM>>>(pW, pb, mask, out);
}

// round 8
// speedup vs baseline: 1.0709x; 1.0709x over previous
#include <cuda_runtime.h>

#define N_NODES 100000
#define N_EDGES 1600000
#define NH 8
#define ND 16
#define HD 128
#define G_GRAPHS 128
#define OUT_DIM 64
#define BN_EPS 1e-3f
#define NEG_SLOPE 0.2f

// ---------------- device scratch (no allocations allowed) ----------------
__device__ float g_feat[N_NODES * HD];    // W-transformed features (per layer, reused)
__device__ float g_agg[N_NODES * HD];     // unnormalized GAT aggregation (per layer)
__device__ float g_h1[N_NODES * HD];      // layer-0 output (residual input)
__device__ float g_el[N_NODES * NH];
__device__ float g_er[N_NODES * NH];
__device__ float g_denom[N_NODES * NH];   // softmax denominators -> inverted in place
__device__ float g_bnsum[HD];
__device__ float g_bnsum2[HD];
__device__ float g_scale[HD];
__device__ float g_shift[HD];
__device__ float g_pooled[G_GRAPHS * HD];

// Vectorized global float4 reduction (sm_90+)
__device__ __forceinline__ void red_add_v4(float* addr, float4 v) {
    asm volatile("red.global.add.v4.f32 [%0], {%1,%2,%3,%4};"
                 :: "l"(addr), "f"(v.x), "f"(v.y), "f"(v.z), "f"(v.w)
                 : "memory");
}

// ---------------- zero scratch ----------------
__global__ void zero_scratch(int zero_pooled) {
    int i = blockIdx.x * blockDim.x + threadIdx.x;
    float4 z = make_float4(0.f, 0.f, 0.f, 0.f);
    if (i < N_NODES * HD / 4) ((float4*)g_agg)[i] = z;
    if (i < N_NODES * NH / 4) ((float4*)g_denom)[i] = z;
    if (i < HD / 4) {
        ((float4*)g_bnsum)[i] = z;
        ((float4*)g_bnsum2)[i] = z;
    }
    if (zero_pooled && i < G_GRAPHS * HD / 4) ((float4*)g_pooled)[i] = z;
}

// ---------------- GEMM: feat = A @ W, A:[N,128] W:[128,128] ----------------
// 64-row x 128-col tile per block, 256 threads, each thread 8x4 outputs.
// f32x2 packed FMA (FFMA2) + transposed A tile (broadcast LDS.128 reads).
__global__ void __launch_bounds__(256) gemm128(const float* __restrict__ Aext,
                                               const float* __restrict__ W,
                                               int use_h1) {
    const float* A = use_h1 ? g_h1 : Aext;
    __shared__ float As[32][68];   // [k][row], stride 68 -> 16B-aligned rows
    __shared__ float Ws[32][128];
    int t = threadIdx.x;
    int r0 = blockIdx.x * 64;
    int cg = (t & 31) * 4;   // column base (0..124)
    int rg = (t >> 5) * 8;   // row base within tile (0..56)

    // acc[i][0] holds cols {cg,cg+1}; acc[i][1] holds {cg+2,cg+3} as packed f32x2
    unsigned long long acc[8][2];
#pragma unroll
    for (int i = 0; i < 8; i++) { acc[i][0] = 0ULL; acc[i][1] = 0ULL; }

    for (int kc = 0; kc < HD; kc += 32) {
        // load A tile 64x32 -> transposed As[k][r]
        for (int i = t; i < 64 * 32; i += 256) {
            int r = i >> 5, k = i & 31;
            int row = r0 + r;
            As[k][r] = (row < N_NODES) ? A[row * HD + kc + k] : 0.f;
        }
        // load W tile 32x128
        for (int i = t; i < 32 * 128; i += 256) {
            int k = i >> 7, c = i & 127;
            Ws[k][c] = W[(kc + k) * HD + c];
        }
        __syncthreads();
#pragma unroll
        for (int k = 0; k < 32; k++) {
            float4 wv = *(const float4*)&Ws[k][cg];
            unsigned long long w01, w23;
            asm("mov.b64 %0, {%1,%2};" : "=l"(w01) : "f"(wv.x), "f"(wv.y));
            asm("mov.b64 %0, {%1,%2};" : "=l"(w23) : "f"(wv.z), "f"(wv.w));
            float4 a03 = *(const float4*)&As[k][rg];
            float4 a47 = *(const float4*)&As[k][rg + 4];
            float ar[8] = {a03.x, a03.y, a03.z, a03.w, a47.x, a47.y, a47.z, a47.w};
#pragma unroll
            for (int i = 0; i < 8; i++) {
                unsigned long long av;
                asm("mov.b64 %0, {%1,%2};" : "=l"(av) : "f"(ar[i]), "f"(ar[i]));
                asm("fma.rn.f32x2 %0, %1, %2, %0;" : "+l"(acc[i][0]) : "l"(av), "l"(w01));
                asm("fma.rn.f32x2 %0, %1, %2, %0;" : "+l"(acc[i][1]) : "l"(av), "l"(w23));
            }
        }
        __syncthreads();
    }
#pragma unroll
    for (int i = 0; i < 8; i++) {
        int row = r0 + rg + i;
        if (row < N_NODES) {
            float x0, x1, x2, x3;
            asm("mov.b64 {%0,%1}, %2;" : "=f"(x0), "=f"(x1) : "l"(acc[i][0]));
            asm("mov.b64 {%0,%1}, %2;" : "=f"(x2), "=f"(x3) : "l"(acc[i][1]));
            *(float4*)&g_feat[row * HD + cg] = make_float4(x0, x1, x2, x3);
        }
    }
}

// ---------------- per-node attention halves: el/er ----------------
__global__ void compute_elr(const float* __restrict__ al, const float* __restrict__ ar) {
    int idx = blockIdx.x * blockDim.x + threadIdx.x;  // (node, head)
    if (idx >= N_NODES * NH) return;
    int h = idx & (NH - 1);
    const float4* f4 = (const float4*)&g_feat[idx * ND];
    const float4* a4 = (const float4*)&al[h * ND];
    const float4* b4 = (const float4*)&ar[h * ND];
    float el = 0.f, er = 0.f;
#pragma unroll
    for (int j = 0; j < 4; j++) {
        float4 f = f4[j];
        float4 a = a4[j];
        float4 b = b4[j];
        el += f.x * a.x + f.y * a.y + f.z * a.z + f.w * a.w;
        er += f.x * b.x + f.y * b.y + f.z * b.z + f.w * b.w;
    }
    g_el[idx] = el;
    g_er[idx] = er;
}

__device__ __forceinline__ float expleaky(float x) {
    x = (x > 0.f) ? x : NEG_SLOPE * x;
    return __expf(x);
}

// ---------------- fused edge pass ----------------
// Softmax division moved to the node side:
//   out[d] = (sum_e ee*feat[src]) / denom[d]   (denom constant per (d,head))
// One warp per edge: lanes 0..7 compute ee per head; scatter ee into denom
// (two v4 reds) and ee*feat[src] into agg (one v4 red per lane).
__global__ void edge_fused(const int* __restrict__ src, const int* __restrict__ dst) {
    int gt = blockIdx.x * blockDim.x + threadIdx.x;
    int gw = gt >> 5;
    int lane = threadIdx.x & 31;
    if (gw >= N_EDGES) return;
    int s = src[gw], d = dst[gw];

    float ee = 0.f;
    if (lane < NH)
        ee = expleaky(g_el[s * NH + lane] + g_er[d * NH + lane]);

    // pack this group's 4 head values for the denom reduction
    int base = lane & 4;  // 0 for heads 0-3 group, 4 for heads 4-7 group
    float e0 = __shfl_sync(0xffffffffu, ee, base + 0);
    float e1 = __shfl_sync(0xffffffffu, ee, base + 1);
    float e2 = __shfl_sync(0xffffffffu, ee, base + 2);
    float e3 = __shfl_sync(0xffffffffu, ee, base + 3);
    if (lane == 0 || lane == 4)
        red_add_v4(&g_denom[d * NH + lane], make_float4(e0, e1, e2, e3));

    int h = lane >> 2;  // head owning channels lane*4 .. lane*4+3
    float myee = __shfl_sync(0xffffffffu, ee, h);
    float4 f = ((const float4*)&g_feat[s * HD])[lane];
    red_add_v4(&g_agg[d * HD + lane * 4],
               make_float4(myee * f.x, myee * f.y, myee * f.z, myee * f.w));
}

// ---------------- invert denominators in place ----------------
// Guard: a node with zero in-edges has denom=0 and agg=0; reference yields 0.
__global__ void invert_denom() {
    int i = blockIdx.x * blockDim.x + threadIdx.x;
    if (i >= N_NODES * NH) return;
    float d = g_denom[i];
    g_denom[i] = (d != 0.f) ? 1.0f / d : 0.f;
}

// ---------------- BatchNorm statistics (on normalized values) ----------------
#define BN_ROWS 512
__global__ void bn_stats() {
    int c = threadIdx.x;  // 128 channels
    int h = c >> 4;
    int r0 = blockIdx.x * BN_ROWS;
    int r1 = min(r0 + BN_ROWS, N_NODES);
    float s = 0.f, s2 = 0.f;
    for (int r = r0; r < r1; r++) {
        float x = g_agg[r * HD + c] * g_denom[r * NH + h];
        s += x;
        s2 += x * x;
    }
    atomicAdd(&g_bnsum[c], s);
    atomicAdd(&g_bnsum2[c], s2);
}

// Note: GAT bias b cancels inside BN (x - mean(x)), so it is never applied.
__global__ void bn_finalize(const float* __restrict__ gm, const float* __restrict__ be) {
    int c = threadIdx.x;
    float inv_n = 1.0f / (float)N_NODES;
    float mu = g_bnsum[c] * inv_n;
    float var = g_bnsum2[c] * inv_n - mu * mu;
    float rs = rsqrtf(var + BN_EPS);
    float sc = rs * gm[c];
    g_scale[c] = sc;
    g_shift[c] = be[c] - mu * sc;
}

// ---------------- layer 0 epilogue: h1 = relu(bn(agg/denom)) ----------------
__global__ void apply_bn_relu() {
    int i = blockIdx.x * blockDim.x + threadIdx.x;  // per float4
    if (i >= N_NODES * HD / 4) return;
    int c4 = i & 31;
    int node = i >> 5;
    float inv = g_denom[node * NH + (c4 >> 2)];
    float4 x = ((const float4*)g_agg)[i];
    float4 sc = ((const float4*)g_scale)[c4];
    float4 sh = ((const float4*)g_shift)[c4];
    x.x = fmaxf(x.x * inv * sc.x + sh.x, 0.f);
    x.y = fmaxf(x.y * inv * sc.y + sh.y, 0.f);
    x.z = fmaxf(x.z * inv * sc.z + sh.z, 0.f);
    x.w = fmaxf(x.w * inv * sc.w + sh.w, 0.f);
    ((float4*)g_h1)[i] = x;
}

// ---------------- layer 1 epilogue fused with sum-pool ----------------
// h2 = relu(bn(agg/denom)) + h1; pooled[gid] += h2. graph_ids are sorted ->
// run-length accumulate in registers, few atomics.
#define POOL_ROWS 512
__global__ void apply_bn_relu_res_pool(const int* __restrict__ gid) {
    int c = threadIdx.x;  // 128 channels
    int h = c >> 4;
    int r0 = blockIdx.x * POOL_ROWS;
    int r1 = min(r0 + POOL_ROWS, N_NODES);
    float sc = g_scale[c], sh = g_shift[c];
    float acc = 0.f;
    int cur = gid[r0];
    for (int r = r0; r < r1; r++) {
        int g = gid[r];
        float inv = g_denom[r * NH + h];
        float x = g_agg[r * HD + c] * inv * sc + sh;
        x = fmaxf(x, 0.f) + g_h1[r * HD + c];
        if (g != cur) {
            atomicAdd(&g_pooled[cur * HD + c], acc);
            acc = 0.f;
            cur = g;
        }
        acc += x;
    }
    atomicAdd(&g_pooled[cur * HD + c], acc);
}

// ---------------- masked prediction head ----------------
__global__ void final_linear(const float* __restrict__ pW, const float* __restrict__ pb,
                             const float* __restrict__ mask, float* __restrict__ out) {
    __shared__ float p[HD];
    int g = blockIdx.x;
    int o = threadIdx.x;  // 64 threads
    p[o] = g_pooled[g * HD + o];
    p[o + 64] = g_pooled[g * HD + o + 64];
    __syncthreads();
    float s = 0.f;
#pragma unroll 4
    for (int c = 0; c < HD; c++) {
        float w = pW[o * HD + c];
        float m = (mask[o * HD + c] > 0.5f) ? 1.f : 0.f;
        s += p[c] * w * m;
    }
    out[g * OUT_DIM + o] = s + pb[o];
}

// ---------------- launch ----------------
extern "C" void kernel_launch(void* const* d_in, const int* in_sizes, int n_in,
                              void* d_out, int out_size) {
    const float* h    = (const float*)d_in[0];
    const int*   src  = (const int*)d_in[1];
    const int*   dst  = (const int*)d_in[2];
    const int*   gid  = (const int*)d_in[3];
    const float* W0   = (const float*)d_in[4];
    const float* al0  = (const float*)d_in[5];
    const float* ar0  = (const float*)d_in[6];
    // d_in[7] = b0 (cancels in BN)
    const float* g0   = (const float*)d_in[8];
    const float* be0  = (const float*)d_in[9];
    const float* W1   = (const float*)d_in[10];
    const float* al1  = (const float*)d_in[11];
    const float* ar1  = (const float*)d_in[12];
    // d_in[13] = b1 (cancels in BN)
    const float* g1   = (const float*)d_in[14];
    const float* be1  = (const float*)d_in[15];
    const float* pW   = (const float*)d_in[16];
    const float* pb   = (const float*)d_in[17];
    const float* mask = (const float*)d_in[18];
    float* out = (float*)d_out;

    const int zgrid   = (N_NODES * HD / 4 + 255) / 256;          // 12500
    const int ggrid   = (N_NODES + 63) / 64;                     // 1563
    const int elrgrid = (N_NODES * NH + 255) / 256;              // 3125
    const int sgrid   = (N_EDGES * 32) / 256;                    // 200000
    const int dgrid   = (N_NODES * NH + 255) / 256;              // 3125
    const int agrid   = (N_NODES * HD / 4 + 255) / 256;          // 12500
    const int bngrid  = (N_NODES + BN_ROWS - 1) / BN_ROWS;       // 196

    // ---- layer 0 ----
    zero_scratch<<<zgrid, 256>>>(1);
    gemm128<<<ggrid, 256>>>(h, W0, 0);
    compute_elr<<<elrgrid, 256>>>(al0, ar0);
    edge_fused<<<sgrid, 256>>>(src, dst);
    invert_denom<<<dgrid, 256>>>();
    bn_stats<<<bngrid, 128>>>();
    bn_finalize<<<1, 128>>>(g0, be0);
    apply_bn_relu<<<agrid, 256>>>();

    // ---- layer 1 ----
    zero_scratch<<<zgrid, 256>>>(0);
    gemm128<<<ggrid, 256>>>(nullptr, W1, 1);
    compute_elr<<<elrgrid, 256>>>(al1, ar1);
    edge_fused<<<sgrid, 256>>>(src, dst);
    invert_denom<<<dgrid, 256>>>();
    bn_stats<<<bngrid, 128>>>();
    bn_finalize<<<1, 128>>>(g1, be1);
    apply_bn_relu_res_pool<<<bngrid, 128>>>(gid);

    // ---- head ----
    final_linear<<<G_GRAPHS, OUT_DIM>>>(pW, pb, mask, out);
}

// round 12
// speedup vs baseline: 1.3194x; 1.2321x over previous
#include <cuda_runtime.h>

#define N_NODES 100000
#define N_EDGES 1600000
#define NH 8
#define ND 16
#define HD 128
#define G_GRAPHS 128
#define OUT_DIM 64
#define BN_EPS 1e-3f
#define NEG_SLOPE 0.2f

// ---------------- device scratch (no allocations allowed) ----------------
__device__ float g_feat[N_NODES * HD];    // W-transformed features (per layer)
__device__ float g_agg[N_NODES * HD];     // normalized GAT aggregation (per layer)
__device__ float g_h1[N_NODES * HD];      // layer-0 output (residual input)
__device__ float g_el[N_NODES * NH];
__device__ float g_er[N_NODES * NH];
__device__ int   g_deg[N_NODES];          // degree histogram
__device__ int   g_cursor[N_NODES];       // scatter cursors
__device__ int   g_off[N_NODES + 1];      // CSR offsets (by dst)
__device__ int   g_esrc[N_EDGES];         // src node per CSR slot
__device__ int   g_blocksum[256];
__device__ float g_bnsum[HD];
__device__ float g_bnsum2[HD];
__device__ float g_scale[HD];
__device__ float g_shift[HD];
__device__ float g_pooled[G_GRAPHS * HD];

__device__ __forceinline__ void red_add_v4(float* addr, float4 v) {
    asm volatile("red.global.add.v4.f32 [%0], {%1,%2,%3,%4};"
                 :: "l"(addr), "f"(v.x), "f"(v.y), "f"(v.z), "f"(v.w)
                 : "memory");
}

// ================= CSR build (src/dst identical both layers: build once) ====
__global__ void csr_zero_deg() {
    int i = blockIdx.x * blockDim.x + threadIdx.x;
    if (i < N_NODES) g_deg[i] = 0;
}

__global__ void csr_hist(const int* __restrict__ dst) {
    int e = blockIdx.x * blockDim.x + threadIdx.x;
    if (e < N_EDGES) atomicAdd(&g_deg[dst[e]], 1);
}

#define SCAN_B 512
#define SCAN_NBLK ((N_NODES + SCAN_B - 1) / SCAN_B)   // 196

__global__ void csr_scan1() {   // per-chunk sums
    __shared__ int sm[SCAN_B];
    int i = blockIdx.x * SCAN_B + threadIdx.x;
    sm[threadIdx.x] = (i < N_NODES) ? g_deg[i] : 0;
    __syncthreads();
    for (int s = SCAN_B / 2; s > 0; s >>= 1) {
        if (threadIdx.x < s) sm[threadIdx.x] += sm[threadIdx.x + s];
        __syncthreads();
    }
    if (threadIdx.x == 0) g_blocksum[blockIdx.x] = sm[0];
}

__global__ void csr_scan2() {   // tiny sequential exclusive scan of chunk sums
    int acc = 0;
    for (int b = 0; b < SCAN_NBLK; b++) {
        int v = g_blocksum[b];
        g_blocksum[b] = acc;
        acc += v;
    }
    g_off[N_NODES] = N_EDGES;
}

__global__ void csr_scan3() {   // in-chunk exclusive scan + chunk offset
    __shared__ int sm[SCAN_B];
    int tid = threadIdx.x;
    int i = blockIdx.x * SCAN_B + tid;
    int v = (i < N_NODES) ? g_deg[i] : 0;
    sm[tid] = v;
    __syncthreads();
    for (int off = 1; off < SCAN_B; off <<= 1) {
        int y = (tid >= off) ? sm[tid - off] : 0;
        __syncthreads();
        sm[tid] += y;
        __syncthreads();
    }
    int excl = sm[tid] - v + g_blocksum[blockIdx.x];
    if (i < N_NODES) {
        g_off[i] = excl;
        g_cursor[i] = excl;
    }
}

__global__ void csr_scatter(const int* __restrict__ src, const int* __restrict__ dst) {
    int e = blockIdx.x * blockDim.x + threadIdx.x;
    if (e < N_EDGES) {
        int p = atomicAdd(&g_cursor[dst[e]], 1);
        g_esrc[p] = src[e];
    }
}

// ---------------- small zero: bn accumulators (+pooled on first call) ------
__global__ void zero_small(int zero_pooled) {
    int i = blockIdx.x * blockDim.x + threadIdx.x;
    float4 z = make_float4(0.f, 0.f, 0.f, 0.f);
    if (i < 32) ((float4*)g_bnsum)[i] = z;
    else if (i < 64) ((float4*)g_bnsum2)[i - 32] = z;
    if (zero_pooled && i < G_GRAPHS * HD / 4) ((float4*)g_pooled)[i] = z;
}

// ---------------- GEMM: feat = A @ W + fused el/er epilogue ----------------
// 64x128 tile, 256 threads, 8x4 outputs/thread, f32x2 packed FMA.
// Epilogue: el[n,h]=dot(feat[n,h*16:+16],al[h]) via quad shuffle-reduce.
__global__ void __launch_bounds__(256) gemm128(const float* __restrict__ Aext,
                                               const float* __restrict__ W,
                                               const float* __restrict__ al,
                                               const float* __restrict__ ar,
                                               int use_h1) {
    const float* A = use_h1 ? g_h1 : Aext;
    __shared__ float As[32][68];   // [k][row]
    __shared__ float Ws[32][128];
    int t = threadIdx.x;
    int r0 = blockIdx.x * 64;
    int lane = t & 31;
    int cg = lane * 4;       // column base (0..124)
    int rg = (t >> 5) * 8;   // row base within tile

    unsigned long long acc[8][2];
#pragma unroll
    for (int i = 0; i < 8; i++) { acc[i][0] = 0ULL; acc[i][1] = 0ULL; }

    for (int kc = 0; kc < HD; kc += 32) {
        for (int i = t; i < 64 * 32; i += 256) {
            int r = i >> 5, k = i & 31;
            int row = r0 + r;
            As[k][r] = (row < N_NODES) ? A[row * HD + kc + k] : 0.f;
        }
        for (int i = t; i < 32 * 128; i += 256) {
            int k = i >> 7, c = i & 127;
            Ws[k][c] = W[(kc + k) * HD + c];
        }
        __syncthreads();
#pragma unroll
        for (int k = 0; k < 32; k++) {
            float4 wv = *(const float4*)&Ws[k][cg];
            unsigned long long w01, w23;
            asm("mov.b64 %0, {%1,%2};" : "=l"(w01) : "f"(wv.x), "f"(wv.y));
            asm("mov.b64 %0, {%1,%2};" : "=l"(w23) : "f"(wv.z), "f"(wv.w));
            float4 a03 = *(const float4*)&As[k][rg];
            float4 a47 = *(const float4*)&As[k][rg + 4];
            float ar8[8] = {a03.x, a03.y, a03.z, a03.w, a47.x, a47.y, a47.z, a47.w};
#pragma unroll
            for (int i = 0; i < 8; i++) {
                unsigned long long av;
                asm("mov.b64 %0, {%1,%2};" : "=l"(av) : "f"(ar8[i]), "f"(ar8[i]));
                asm("fma.rn.f32x2 %0, %1, %2, %0;" : "+l"(acc[i][0]) : "l"(av), "l"(w01));
                asm("fma.rn.f32x2 %0, %1, %2, %0;" : "+l"(acc[i][1]) : "l"(av), "l"(w23));
            }
        }
        __syncthreads();
    }

    int head = cg >> 4;
    int coff = cg & 15;
    float4 alv = *(const float4*)&al[head * ND + coff];
    float4 arv = *(const float4*)&ar[head * ND + coff];

#pragma unroll
    for (int i = 0; i < 8; i++) {
        int row = r0 + rg + i;
        float x0, x1, x2, x3;
        asm("mov.b64 {%0,%1}, %2;" : "=f"(x0), "=f"(x1) : "l"(acc[i][0]));
        asm("mov.b64 {%0,%1}, %2;" : "=f"(x2), "=f"(x3) : "l"(acc[i][1]));
        if (row < N_NODES)
            *(float4*)&g_feat[row * HD + cg] = make_float4(x0, x1, x2, x3);
        // fused el/er: partial dot over this thread's 4 channels, quad-reduce
        float elp = x0 * alv.x + x1 * alv.y + x2 * alv.z + x3 * alv.w;
        float erp = x0 * arv.x + x1 * arv.y + x2 * arv.z + x3 * arv.w;
        elp += __shfl_xor_sync(0xffffffffu, elp, 1);
        elp += __shfl_xor_sync(0xffffffffu, elp, 2);
        erp += __shfl_xor_sync(0xffffffffu, erp, 1);
        erp += __shfl_xor_sync(0xffffffffu, erp, 2);
        if ((lane & 3) == 0 && row < N_NODES) {
            g_el[row * NH + head] = elp;
            g_er[row * NH + head] = erp;
        }
    }
}

__device__ __forceinline__ float expleaky(float x) {
    x = (x > 0.f) ? x : NEG_SLOPE * x;
    return __expf(x);
}

// ---------------- CSR gather: softmax-weighted aggregation, no atomics -----
// One warp per GN consecutive dst nodes. Lanes 0-7 own per-head ee/denom;
// all 32 lanes accumulate 4 channels each. Fuses normalization + BN moments.
#define GN 8
__global__ void __launch_bounds__(256) gat_gather() {
    int lane = threadIdx.x & 31;
    int wid = (blockIdx.x * blockDim.x + threadIdx.x) >> 5;
    int n0 = wid * GN;
    if (n0 >= N_NODES) return;
    int h = lane >> 2;
    float4 bs = make_float4(0.f, 0.f, 0.f, 0.f);
    float4 bs2 = make_float4(0.f, 0.f, 0.f, 0.f);
    int nend = min(n0 + GN, N_NODES);

    for (int d = n0; d < nend; d++) {
        float er_h = (lane < NH) ? g_er[d * NH + lane] : 0.f;
        int beg = g_off[d], end = g_off[d + 1];
        float4 acc = make_float4(0.f, 0.f, 0.f, 0.f);
        float den = 0.f;
        int s = (beg < end) ? g_esrc[beg] : 0;
        for (int j = beg; j < end; j++) {
            int scur = s;
            if (j + 1 < end) s = g_esrc[j + 1];   // prefetch next src
            float ee = 0.f;
            if (lane < NH) ee = expleaky(g_el[scur * NH + lane] + er_h);
            float myee = __shfl_sync(0xffffffffu, ee, h);
            float4 f = ((const float4*)g_feat)[scur * 32 + lane];
            acc.x += myee * f.x;
            acc.y += myee * f.y;
            acc.z += myee * f.z;
            acc.w += myee * f.w;
            den += ee;
        }
        float dsum = __shfl_sync(0xffffffffu, den, h);
        float inv = (dsum != 0.f) ? 1.0f / dsum : 0.f;
        acc.x *= inv; acc.y *= inv; acc.z *= inv; acc.w *= inv;
        ((float4*)g_agg)[d * 32 + lane] = acc;
        bs.x += acc.x; bs.y += acc.y; bs.z += acc.z; bs.w += acc.w;
        bs2.x += acc.x * acc.x; bs2.y += acc.y * acc.y;
        bs2.z += acc.z * acc.z; bs2.w += acc.w * acc.w;
    }
    red_add_v4(&g_bnsum[lane * 4], bs);
    red_add_v4(&g_bnsum2[lane * 4], bs2);
}

// Note: GAT bias b cancels inside BN (x - mean(x)), so it is never applied.
__global__ void bn_finalize(const float* __restrict__ gm, const float* __restrict__ be) {
    int c = threadIdx.x;
    float inv_n = 1.0f / (float)N_NODES;
    float mu = g_bnsum[c] * inv_n;
    float var = g_bnsum2[c] * inv_n - mu * mu;
    float rs = rsqrtf(var + BN_EPS);
    float sc = rs * gm[c];
    g_scale[c] = sc;
    g_shift[c] = be[c] - mu * sc;
}

// ---------------- layer 0 epilogue: h1 = relu(bn(agg)) ----------------
__global__ void apply_bn_relu() {
    int i = blockIdx.x * blockDim.x + threadIdx.x;  // per float4
    if (i >= N_NODES * HD / 4) return;
    int c4 = i & 31;
    float4 x = ((const float4*)g_agg)[i];
    float4 sc = ((const float4*)g_scale)[c4];
    float4 sh = ((const float4*)g_shift)[c4];
    x.x = fmaxf(x.x * sc.x + sh.x, 0.f);
    x.y = fmaxf(x.y * sc.y + sh.y, 0.f);
    x.z = fmaxf(x.z * sc.z + sh.z, 0.f);
    x.w = fmaxf(x.w * sc.w + sh.w, 0.f);
    ((float4*)g_h1)[i] = x;
}

// ---------------- layer 1 epilogue fused with sum-pool ----------------
#define POOL_ROWS 512
__global__ void apply_bn_relu_res_pool(const int* __restrict__ gid) {
    int c = threadIdx.x;  // 128 channels
    int r0 = blockIdx.x * POOL_ROWS;
    int r1 = min(r0 + POOL_ROWS, N_NODES);
    float sc = g_scale[c], sh = g_shift[c];
    float acc = 0.f;
    int cur = gid[r0];
    for (int r = r0; r < r1; r++) {
        int g = gid[r];
        float x = g_agg[r * HD + c] * sc + sh;
        x = fmaxf(x, 0.f) + g_h1[r * HD + c];
        if (g != cur) {
            atomicAdd(&g_pooled[cur * HD + c], acc);
            acc = 0.f;
            cur = g;
        }
        acc += x;
    }
    atomicAdd(&g_pooled[cur * HD + c], acc);
}

// ---------------- masked prediction head ----------------
__global__ void final_linear(const float* __restrict__ pW, const float* __restrict__ pb,
                             const float* __restrict__ mask, float* __restrict__ out) {
    __shared__ float p[HD];
    int g = blockIdx.x;
    int o = threadIdx.x;  // 64 threads
    p[o] = g_pooled[g * HD + o];
    p[o + 64] = g_pooled[g * HD + o + 64];
    __syncthreads();
    float s = 0.f;
#pragma unroll 4
    for (int c = 0; c < HD; c++) {
        float w = pW[o * HD + c];
        float m = (mask[o * HD + c] > 0.5f) ? 1.f : 0.f;
        s += p[c] * w * m;
    }
    out[g * OUT_DIM + o] = s + pb[o];
}

// ---------------- launch ----------------
extern "C" void kernel_launch(void* const* d_in, const int* in_sizes, int n_in,
                              void* d_out, int out_size) {
    const float* h    = (const float*)d_in[0];
    const int*   src  = (const int*)d_in[1];
    const int*   dst  = (const int*)d_in[2];
    const int*   gid  = (const int*)d_in[3];
    const float* W0   = (const float*)d_in[4];
    const float* al0  = (const float*)d_in[5];
    const float* ar0  = (const float*)d_in[6];
    // d_in[7] = b0 (cancels in BN)
    const float* g0   = (const float*)d_in[8];
    const float* be0  = (const float*)d_in[9];
    const float* W1   = (const float*)d_in[10];
    const float* al1  = (const float*)d_in[11];
    const float* ar1  = (const float*)d_in[12];
    // d_in[13] = b1 (cancels in BN)
    const float* g1   = (const float*)d_in[14];
    const float* be1  = (const float*)d_in[15];
    const float* pW   = (const float*)d_in[16];
    const float* pb   = (const float*)d_in[17];
    const float* mask = (const float*)d_in[18];
    float* out = (float*)d_out;

    const int ggrid   = (N_NODES + 63) / 64;                       // 1563
    const int egrid   = (N_EDGES + 255) / 256;                     // 6250
    const int ngrid   = (N_NODES + 255) / 256;                     // 391
    const int wgrid   = (N_NODES + 8 * GN * 32 - 1) / (8 * GN);    // warp-gather blocks
    const int gagrid  = (N_NODES / (8 * GN)) + 1;                  // 1563
    const int agrid   = (N_NODES * HD / 4 + 255) / 256;            // 12500
    const int pgrid   = (N_NODES + POOL_ROWS - 1) / POOL_ROWS;     // 196
    (void)wgrid;

    // ---- CSR build (edges identical across layers: once per call) ----
    csr_zero_deg<<<ngrid, 256>>>();
    csr_hist<<<egrid, 256>>>(dst);
    csr_scan1<<<SCAN_NBLK, SCAN_B>>>();
    csr_scan2<<<1, 1>>>();
    csr_scan3<<<SCAN_NBLK, SCAN_B>>>();
    csr_scatter<<<egrid, 256>>>(src, dst);

    // ---- layer 0 ----
    zero_small<<<17, 256>>>(1);
    gemm128<<<ggrid, 256>>>(h, W0, al0, ar0, 0);
    gat_gather<<<gagrid, 256>>>();
    bn_finalize<<<1, 128>>>(g0, be0);
    apply_bn_relu<<<agrid, 256>>>();

    // ---- layer 1 ----
    zero_small<<<17, 256>>>(0);
    gemm128<<<ggrid, 256>>>(nullptr, W1, al1, ar1, 1);
    gat_gather<<<gagrid, 256>>>();
    bn_finalize<<<1, 128>>>(g1, be1);
    apply_bn_relu_res_pool<<<pgrid, 128>>>(gid);

    // ---- head ----
    final_linear<<<G_GRAPHS, OUT_DIM>>>(pW, pb, mask, out);
}

// round 13
// speedup vs baseline: 1.4697x; 1.1139x over previous
#include <cuda_runtime.h>

#define N_NODES 100000
#define N_EDGES 1600000
#define NH 8
#define ND 16
#define HD 128
#define G_GRAPHS 128
#define OUT_DIM 64
#define BN_EPS 1e-3f
#define NEG_SLOPE 0.2f

// ---------------- device scratch (no allocations allowed) ----------------
__device__ float g_feat[N_NODES * HD];    // W-transformed features (per layer)
__device__ float g_agg[N_NODES * HD];     // normalized GAT aggregation (per layer)
__device__ float g_h1[N_NODES * HD];      // layer-0 output (residual input)
__device__ float g_el[N_NODES * NH];
__device__ float g_er[N_NODES * NH];
__device__ int   g_deg[N_NODES];          // degree histogram
__device__ int   g_cursor[N_NODES];       // scatter cursors
__device__ int   g_off[N_NODES + 1];      // CSR offsets (by dst)
__device__ int   g_esrc[N_EDGES];         // src node per CSR slot
__device__ int   g_blocksum[256];
__device__ float g_bnsum[2 * HD];         // per-layer BN accumulators
__device__ float g_bnsum2[2 * HD];
__device__ float g_scale[HD];
__device__ float g_shift[HD];
__device__ float g_pooled[G_GRAPHS * HD];

__device__ __forceinline__ void red_add_v4(float* addr, float4 v) {
    asm volatile("red.global.add.v4.f32 [%0], {%1,%2,%3,%4};"
                 :: "l"(addr), "f"(v.x), "f"(v.y), "f"(v.z), "f"(v.w)
                 : "memory");
}

// ---------------- one upfront zero pass (side stream) ----------------
// Zeros: g_deg (25000 int4), both BN accumulator sets, g_pooled.
__global__ void zero_all() {
    int i = blockIdx.x * blockDim.x + threadIdx.x;
    int4 zi = make_int4(0, 0, 0, 0);
    float4 z = make_float4(0.f, 0.f, 0.f, 0.f);
    if (i < N_NODES / 4) ((int4*)g_deg)[i] = zi;
    if (i < 2 * HD / 4) {
        ((float4*)g_bnsum)[i] = z;
        ((float4*)g_bnsum2)[i] = z;
    }
    if (i < G_GRAPHS * HD / 4) ((float4*)g_pooled)[i] = z;
}

// ================= CSR build (src/dst identical both layers) ====
__global__ void csr_hist(const int* __restrict__ dst) {
    int e = blockIdx.x * blockDim.x + threadIdx.x;
    if (e < N_EDGES) atomicAdd(&g_deg[dst[e]], 1);
}

#define SCAN_B 512
#define SCAN_NBLK ((N_NODES + SCAN_B - 1) / SCAN_B)   // 196

__global__ void csr_scan1() {   // per-chunk sums
    __shared__ int sm[SCAN_B];
    int i = blockIdx.x * SCAN_B + threadIdx.x;
    sm[threadIdx.x] = (i < N_NODES) ? g_deg[i] : 0;
    __syncthreads();
    for (int s = SCAN_B / 2; s > 0; s >>= 1) {
        if (threadIdx.x < s) sm[threadIdx.x] += sm[threadIdx.x + s];
        __syncthreads();
    }
    if (threadIdx.x == 0) g_blocksum[blockIdx.x] = sm[0];
}

// parallel exclusive scan of the 196 chunk sums (one 256-thread block)
__global__ void csr_scan2() {
    __shared__ int sm[256];
    int t = threadIdx.x;
    int v = (t < SCAN_NBLK) ? g_blocksum[t] : 0;
    sm[t] = v;
    __syncthreads();
    for (int off = 1; off < 256; off <<= 1) {
        int y = (t >= off) ? sm[t - off] : 0;
        __syncthreads();
        sm[t] += y;
        __syncthreads();
    }
    if (t < SCAN_NBLK) g_blocksum[t] = sm[t] - v;   // exclusive
    if (t == 0) g_off[N_NODES] = N_EDGES;
}

__global__ void csr_scan3() {   // in-chunk exclusive scan + chunk offset
    __shared__ int sm[SCAN_B];
    int tid = threadIdx.x;
    int i = blockIdx.x * SCAN_B + tid;
    int v = (i < N_NODES) ? g_deg[i] : 0;
    sm[tid] = v;
    __syncthreads();
    for (int off = 1; off < SCAN_B; off <<= 1) {
        int y = (tid >= off) ? sm[tid - off] : 0;
        __syncthreads();
        sm[tid] += y;
        __syncthreads();
    }
    int excl = sm[tid] - v + g_blocksum[blockIdx.x];
    if (i < N_NODES) {
        g_off[i] = excl;
        g_cursor[i] = excl;
    }
}

__global__ void csr_scatter(const int* __restrict__ src, const int* __restrict__ dst) {
    int e = blockIdx.x * blockDim.x + threadIdx.x;
    if (e < N_EDGES) {
        int p = atomicAdd(&g_cursor[dst[e]], 1);
        g_esrc[p] = src[e];
    }
}

// ---------------- GEMM: feat = A @ W + fused el/er epilogue ----------------
// 64x128 tile, 256 threads, 8x4 outputs/thread, f32x2 packed FMA.
// apply_bn=1 (layer 1): A-loader applies relu(agg*scale+shift), writes g_h1.
// Epilogue: el/er per (node,head) via quad shuffle-reduce.
__global__ void __launch_bounds__(256) gemm128(const float* __restrict__ Aext,
                                               const float* __restrict__ W,
                                               const float* __restrict__ al,
                                               const float* __restrict__ ar,
                                               int apply_bn) {
    __shared__ float As[32][68];   // [k][row]
    __shared__ float Ws[32][128];
    int t = threadIdx.x;
    int r0 = blockIdx.x * 64;
    int lane = t & 31;
    int cg = lane * 4;       // column base (0..124)
    int rg = (t >> 5) * 8;   // row base within tile

    unsigned long long acc[8][2];
#pragma unroll
    for (int i = 0; i < 8; i++) { acc[i][0] = 0ULL; acc[i][1] = 0ULL; }

    for (int kc = 0; kc < HD; kc += 32) {
        if (apply_bn) {
            for (int i = t; i < 64 * 32; i += 256) {
                int r = i >> 5, k = i & 31;
                int row = r0 + r;
                int c = kc + k;
                float x = 0.f;
                if (row < N_NODES) {
                    x = fmaxf(g_agg[row * HD + c] * g_scale[c] + g_shift[c], 0.f);
                    g_h1[row * HD + c] = x;   // residual input, stored once
                }
                As[k][r] = x;
            }
        } else {
            for (int i = t; i < 64 * 32; i += 256) {
                int r = i >> 5, k = i & 31;
                int row = r0 + r;
                As[k][r] = (row < N_NODES) ? Aext[row * HD + kc + k] : 0.f;
            }
        }
        for (int i = t; i < 32 * 128; i += 256) {
            int k = i >> 7, c = i & 127;
            Ws[k][c] = W[(kc + k) * HD + c];
        }
        __syncthreads();
#pragma unroll
        for (int k = 0; k < 32; k++) {
            float4 wv = *(const float4*)&Ws[k][cg];
            unsigned long long w01, w23;
            asm("mov.b64 %0, {%1,%2};" : "=l"(w01) : "f"(wv.x), "f"(wv.y));
            asm("mov.b64 %0, {%1,%2};" : "=l"(w23) : "f"(wv.z), "f"(wv.w));
            float4 a03 = *(const float4*)&As[k][rg];
            float4 a47 = *(const float4*)&As[k][rg + 4];
            float ar8[8] = {a03.x, a03.y, a03.z, a03.w, a47.x, a47.y, a47.z, a47.w};
#pragma unroll
            for (int i = 0; i < 8; i++) {
                unsigned long long av;
                asm("mov.b64 %0, {%1,%2};" : "=l"(av) : "f"(ar8[i]), "f"(ar8[i]));
                asm("fma.rn.f32x2 %0, %1, %2, %0;" : "+l"(acc[i][0]) : "l"(av), "l"(w01));
                asm("fma.rn.f32x2 %0, %1, %2, %0;" : "+l"(acc[i][1]) : "l"(av), "l"(w23));
            }
        }
        __syncthreads();
    }

    int head = cg >> 4;
    int coff = cg & 15;
    float4 alv = *(const float4*)&al[head * ND + coff];
    float4 arv = *(const float4*)&ar[head * ND + coff];

#pragma unroll
    for (int i = 0; i < 8; i++) {
        int row = r0 + rg + i;
        float x0, x1, x2, x3;
        asm("mov.b64 {%0,%1}, %2;" : "=f"(x0), "=f"(x1) : "l"(acc[i][0]));
        asm("mov.b64 {%0,%1}, %2;" : "=f"(x2), "=f"(x3) : "l"(acc[i][1]));
        if (row < N_NODES)
            *(float4*)&g_feat[row * HD + cg] = make_float4(x0, x1, x2, x3);
        float elp = x0 * alv.x + x1 * alv.y + x2 * alv.z + x3 * alv.w;
        float erp = x0 * arv.x + x1 * arv.y + x2 * arv.z + x3 * arv.w;
        elp += __shfl_xor_sync(0xffffffffu, elp, 1);
        elp += __shfl_xor_sync(0xffffffffu, elp, 2);
        erp += __shfl_xor_sync(0xffffffffu, erp, 1);
        erp += __shfl_xor_sync(0xffffffffu, erp, 2);
        if ((lane & 3) == 0 && row < N_NODES) {
            g_el[row * NH + head] = elp;
            g_er[row * NH + head] = erp;
        }
    }
}

__device__ __forceinline__ float expleaky(float x) {
    x = (x > 0.f) ? x : NEG_SLOPE * x;
    return __expf(x);
}

// ---------------- CSR gather: softmax-weighted aggregation, no atomics -----
// One warp per GN consecutive dst nodes; 2-edge unrolled for load MLP.
#define GN 8
__global__ void __launch_bounds__(256) gat_gather(int li) {
    int lane = threadIdx.x & 31;
    int wid = (blockIdx.x * blockDim.x + threadIdx.x) >> 5;
    int n0 = wid * GN;
    if (n0 >= N_NODES) return;
    int h = lane >> 2;
    float4 bs = make_float4(0.f, 0.f, 0.f, 0.f);
    float4 bs2 = make_float4(0.f, 0.f, 0.f, 0.f);
    int nend = min(n0 + GN, N_NODES);

    for (int d = n0; d < nend; d++) {
        float er_h = (lane < NH) ? g_er[d * NH + lane] : 0.f;
        int beg = g_off[d], end = g_off[d + 1];
        float4 acc = make_float4(0.f, 0.f, 0.f, 0.f);
        float den = 0.f;
        int j = beg;
        for (; j + 2 <= end; j += 2) {
            int s0 = g_esrc[j], s1 = g_esrc[j + 1];
            float ee0 = 0.f, ee1 = 0.f;
            if (lane < NH) {
                ee0 = expleaky(g_el[s0 * NH + lane] + er_h);
                ee1 = expleaky(g_el[s1 * NH + lane] + er_h);
            }
            float4 f0 = ((const float4*)g_feat)[s0 * 32 + lane];
            float4 f1 = ((const float4*)g_feat)[s1 * 32 + lane];
            float m0 = __shfl_sync(0xffffffffu, ee0, h);
            float m1 = __shfl_sync(0xffffffffu, ee1, h);
            acc.x += m0 * f0.x + m1 * f1.x;
            acc.y += m0 * f0.y + m1 * f1.y;
            acc.z += m0 * f0.z + m1 * f1.z;
            acc.w += m0 * f0.w + m1 * f1.w;
            den += ee0 + ee1;
        }
        if (j < end) {
            int s0 = g_esrc[j];
            float ee0 = 0.f;
            if (lane < NH) ee0 = expleaky(g_el[s0 * NH + lane] + er_h);
            float4 f0 = ((const float4*)g_feat)[s0 * 32 + lane];
            float m0 = __shfl_sync(0xffffffffu, ee0, h);
            acc.x += m0 * f0.x; acc.y += m0 * f0.y;
            acc.z += m0 * f0.z; acc.w += m0 * f0.w;
            den += ee0;
        }
        float dsum = __shfl_sync(0xffffffffu, den, h);
        float inv = (dsum != 0.f) ? 1.0f / dsum : 0.f;
        acc.x *= inv; acc.y *= inv; acc.z *= inv; acc.w *= inv;
        ((float4*)g_agg)[d * 32 + lane] = acc;
        bs.x += acc.x; bs.y += acc.y; bs.z += acc.z; bs.w += acc.w;
        bs2.x += acc.x * acc.x; bs2.y += acc.y * acc.y;
        bs2.z += acc.z * acc.z; bs2.w += acc.w * acc.w;
    }
    red_add_v4(&g_bnsum[li * HD + lane * 4], bs);
    red_add_v4(&g_bnsum2[li * HD + lane * 4], bs2);
}

// Note: GAT bias b cancels inside BN (x - mean(x)), so it is never applied.
__global__ void bn_finalize(const float* __restrict__ gm, const float* __restrict__ be, int li) {
    int c = threadIdx.x;
    float inv_n = 1.0f / (float)N_NODES;
    float mu = g_bnsum[li * HD + c] * inv_n;
    float var = g_bnsum2[li * HD + c] * inv_n - mu * mu;
    float rs = rsqrtf(var + BN_EPS);
    float sc = rs * gm[c];
    g_scale[c] = sc;
    g_shift[c] = be[c] - mu * sc;
}

// ---------------- layer 1 epilogue fused with sum-pool ----------------
#define POOL_ROWS 512
__global__ void apply_bn_relu_res_pool(const int* __restrict__ gid) {
    int c = threadIdx.x;  // 128 channels
    int r0 = blockIdx.x * POOL_ROWS;
    int r1 = min(r0 + POOL_ROWS, N_NODES);
    float sc = g_scale[c], sh = g_shift[c];
    float acc = 0.f;
    int cur = gid[r0];
    for (int r = r0; r < r1; r++) {
        int g = gid[r];
        float x = g_agg[r * HD + c] * sc + sh;
        x = fmaxf(x, 0.f) + g_h1[r * HD + c];
        if (g != cur) {
            atomicAdd(&g_pooled[cur * HD + c], acc);
            acc = 0.f;
            cur = g;
        }
        acc += x;
    }
    atomicAdd(&g_pooled[cur * HD + c], acc);
}

// ---------------- masked prediction head ----------------
__global__ void final_linear(const float* __restrict__ pW, const float* __restrict__ pb,
                             const float* __restrict__ mask, float* __restrict__ out) {
    __shared__ float p[HD];
    int g = blockIdx.x;
    int o = threadIdx.x;  // 64 threads
    p[o] = g_pooled[g * HD + o];
    p[o + 64] = g_pooled[g * HD + o + 64];
    __syncthreads();
    float s = 0.f;
#pragma unroll 4
    for (int c = 0; c < HD; c++) {
        float w = pW[o * HD + c];
        float m = (mask[o * HD + c] > 0.5f) ? 1.f : 0.f;
        s += p[c] * w * m;
    }
    out[g * OUT_DIM + o] = s + pb[o];
}

// ---------------- launch ----------------
extern "C" void kernel_launch(void* const* d_in, const int* in_sizes, int n_in,
                              void* d_out, int out_size) {
    const float* h    = (const float*)d_in[0];
    const int*   src  = (const int*)d_in[1];
    const int*   dst  = (const int*)d_in[2];
    const int*   gid  = (const int*)d_in[3];
    const float* W0   = (const float*)d_in[4];
    const float* al0  = (const float*)d_in[5];
    const float* ar0  = (const float*)d_in[6];
    // d_in[7] = b0 (cancels in BN)
    const float* g0   = (const float*)d_in[8];
    const float* be0  = (const float*)d_in[9];
    const float* W1   = (const float*)d_in[10];
    const float* al1  = (const float*)d_in[11];
    const float* ar1  = (const float*)d_in[12];
    // d_in[13] = b1 (cancels in BN)
    const float* g1   = (const float*)d_in[14];
    const float* be1  = (const float*)d_in[15];
    const float* pW   = (const float*)d_in[16];
    const float* pb   = (const float*)d_in[17];
    const float* mask = (const float*)d_in[18];
    float* out = (float*)d_out;

    // one-time side stream + fork/join events (resource creation only;
    // identical work is launched on every call)
    static cudaStream_t s_side = nullptr;
    static cudaEvent_t e_fork = nullptr, e_join = nullptr;
    if (s_side == nullptr) {
        cudaStreamCreateWithFlags(&s_side, cudaStreamNonBlocking);
        cudaEventCreateWithFlags(&e_fork, cudaEventDisableTiming);
        cudaEventCreateWithFlags(&e_join, cudaEventDisableTiming);
    }

    const int ggrid  = (N_NODES + 63) / 64;                  // 1563
    const int egrid  = (N_EDGES + 255) / 256;                // 6250
    const int zgrid  = (N_NODES / 4 + 255) / 256;            // 98
    const int gagrid = (N_NODES / (8 * GN)) + 1;             // 1563
    const int pgrid  = (N_NODES + POOL_ROWS - 1) / POOL_ROWS;// 196

    // ---- fork: CSR build + zeroing on side stream, overlapped with gemm0 ----
    cudaEventRecord(e_fork, 0);
    cudaStreamWaitEvent(s_side, e_fork, 0);
    zero_all<<<zgrid, 256, 0, s_side>>>();
    csr_hist<<<egrid, 256, 0, s_side>>>(dst);
    csr_scan1<<<SCAN_NBLK, SCAN_B, 0, s_side>>>();
    csr_scan2<<<1, 256, 0, s_side>>>();
    csr_scan3<<<SCAN_NBLK, SCAN_B, 0, s_side>>>();
    csr_scatter<<<egrid, 256, 0, s_side>>>(src, dst);
    cudaEventRecord(e_join, s_side);

    // ---- layer 0 (gemm0 runs concurrently with CSR build) ----
    gemm128<<<ggrid, 256>>>(h, W0, al0, ar0, 0);
    cudaStreamWaitEvent(0, e_join, 0);
    gat_gather<<<gagrid, 256>>>(0);
    bn_finalize<<<1, 128>>>(g0, be0, 0);

    // ---- layer 1 (bn+relu of layer 0 fused into gemm1's A loader) ----
    gemm128<<<ggrid, 256>>>(nullptr, W1, al1, ar1, 1);
    gat_gather<<<gagrid, 256>>>(1);
    bn_finalize<<<1, 128>>>(g1, be1, 1);
    apply_bn_relu_res_pool<<<pgrid, 128>>>(gid);

    // ---- head ----
    final_linear<<<G_GRAPHS, OUT_DIM>>>(pW, pb, mask, out);
}

// round 16
// speedup vs baseline: 1.5321x; 1.0424x over previous
#include <cuda_runtime.h>

#define N_NODES 100000
#define N_EDGES 1600000
#define NH 8
#define ND 16
#define HD 128
#define G_GRAPHS 128
#define OUT_DIM 64
#define BN_EPS 1e-3f
#define NEG_SLOPE 0.2f

// ---------------- device scratch (no allocations allowed) ----------------
__device__ float g_feat[N_NODES * HD];    // W-transformed features (per layer)
__device__ float g_agg[N_NODES * HD];     // normalized GAT aggregation (per layer)
__device__ float g_h1[N_NODES * HD];      // layer-0 output (residual input)
__device__ float g_el[N_NODES * NH];
__device__ float g_er[N_NODES * NH];
__device__ int   g_deg[N_NODES];          // degree histogram
__device__ int   g_cursor[N_NODES];       // scatter cursors
__device__ int   g_off[N_NODES + 1];      // CSR offsets (by dst)
__device__ int   g_esrc[N_EDGES];         // src node per CSR slot
__device__ int   g_blocksum[256];
__device__ float g_bnsum[2 * HD];         // per-layer BN accumulators
__device__ float g_bnsum2[2 * HD];
__device__ float g_scale[HD];
__device__ float g_shift[HD];
__device__ float g_pooled[G_GRAPHS * HD];

__device__ __forceinline__ void red_add_v4(float* addr, float4 v) {
    asm volatile("red.global.add.v4.f32 [%0], {%1,%2,%3,%4};"
                 :: "l"(addr), "f"(v.x), "f"(v.y), "f"(v.z), "f"(v.w)
                 : "memory");
}

// ---------------- one upfront zero pass (side stream) ----------------
__global__ void zero_all() {
    int i = blockIdx.x * blockDim.x + threadIdx.x;
    int4 zi = make_int4(0, 0, 0, 0);
    float4 z = make_float4(0.f, 0.f, 0.f, 0.f);
    if (i < N_NODES / 4) ((int4*)g_deg)[i] = zi;
    if (i < 2 * HD / 4) {
        ((float4*)g_bnsum)[i] = z;
        ((float4*)g_bnsum2)[i] = z;
    }
    if (i < G_GRAPHS * HD / 4) ((float4*)g_pooled)[i] = z;
}

// ================= CSR build (src/dst identical both layers) ====
__global__ void csr_hist(const int* __restrict__ dst) {
    int e = blockIdx.x * blockDim.x + threadIdx.x;
    if (e < N_EDGES) atomicAdd(&g_deg[dst[e]], 1);
}

#define SCAN_B 512
#define SCAN_NBLK ((N_NODES + SCAN_B - 1) / SCAN_B)   // 196

__global__ void csr_scan1() {   // per-chunk sums
    __shared__ int sm[SCAN_B];
    int i = blockIdx.x * SCAN_B + threadIdx.x;
    sm[threadIdx.x] = (i < N_NODES) ? g_deg[i] : 0;
    __syncthreads();
    for (int s = SCAN_B / 2; s > 0; s >>= 1) {
        if (threadIdx.x < s) sm[threadIdx.x] += sm[threadIdx.x + s];
        __syncthreads();
    }
    if (threadIdx.x == 0) g_blocksum[blockIdx.x] = sm[0];
}

__global__ void csr_scan2() {   // parallel exclusive scan of chunk sums
    __shared__ int sm[256];
    int t = threadIdx.x;
    int v = (t < SCAN_NBLK) ? g_blocksum[t] : 0;
    sm[t] = v;
    __syncthreads();
    for (int off = 1; off < 256; off <<= 1) {
        int y = (t >= off) ? sm[t - off] : 0;
        __syncthreads();
        sm[t] += y;
        __syncthreads();
    }
    if (t < SCAN_NBLK) g_blocksum[t] = sm[t] - v;   // exclusive
    if (t == 0) g_off[N_NODES] = N_EDGES;
}

__global__ void csr_scan3() {   // in-chunk exclusive scan + chunk offset
    __shared__ int sm[SCAN_B];
    int tid = threadIdx.x;
    int i = blockIdx.x * SCAN_B + tid;
    int v = (i < N_NODES) ? g_deg[i] : 0;
    sm[tid] = v;
    __syncthreads();
    for (int off = 1; off < SCAN_B; off <<= 1) {
        int y = (tid >= off) ? sm[tid - off] : 0;
        __syncthreads();
        sm[tid] += y;
        __syncthreads();
    }
    int excl = sm[tid] - v + g_blocksum[blockIdx.x];
    if (i < N_NODES) {
        g_off[i] = excl;
        g_cursor[i] = excl;
    }
}

__global__ void csr_scatter(const int* __restrict__ src, const int* __restrict__ dst) {
    int e = blockIdx.x * blockDim.x + threadIdx.x;
    if (e < N_EDGES) {
        int p = atomicAdd(&g_cursor[dst[e]], 1);
        g_esrc[p] = src[e];
    }
}

// ---------------- GEMM: feat = A @ W + fused el/er epilogue ----------------
__global__ void __launch_bounds__(256) gemm128(const float* __restrict__ Aext,
                                               const float* __restrict__ W,
                                               const float* __restrict__ al,
                                               const float* __restrict__ ar,
                                               int apply_bn) {
    __shared__ float As[32][68];   // [k][row]
    __shared__ float Ws[32][128];
    int t = threadIdx.x;
    int r0 = blockIdx.x * 64;
    int lane = t & 31;
    int cg = lane * 4;
    int rg = (t >> 5) * 8;

    unsigned long long acc[8][2];
#pragma unroll
    for (int i = 0; i < 8; i++) { acc[i][0] = 0ULL; acc[i][1] = 0ULL; }

    for (int kc = 0; kc < HD; kc += 32) {
        if (apply_bn) {
            for (int i = t; i < 64 * 32; i += 256) {
                int r = i >> 5, k = i & 31;
                int row = r0 + r;
                int c = kc + k;
                float x = 0.f;
                if (row < N_NODES) {
                    x = fmaxf(g_agg[row * HD + c] * g_scale[c] + g_shift[c], 0.f);
                    g_h1[row * HD + c] = x;
                }
                As[k][r] = x;
            }
        } else {
            for (int i = t; i < 64 * 32; i += 256) {
                int r = i >> 5, k = i & 31;
                int row = r0 + r;
                As[k][r] = (row < N_NODES) ? Aext[row * HD + kc + k] : 0.f;
            }
        }
        for (int i = t; i < 32 * 128; i += 256) {
            int k = i >> 7, c = i & 127;
            Ws[k][c] = W[(kc + k) * HD + c];
        }
        __syncthreads();
#pragma unroll
        for (int k = 0; k < 32; k++) {
            float4 wv = *(const float4*)&Ws[k][cg];
            unsigned long long w01, w23;
            asm("mov.b64 %0, {%1,%2};" : "=l"(w01) : "f"(wv.x), "f"(wv.y));
            asm("mov.b64 %0, {%1,%2};" : "=l"(w23) : "f"(wv.z), "f"(wv.w));
            float4 a03 = *(const float4*)&As[k][rg];
            float4 a47 = *(const float4*)&As[k][rg + 4];
            float ar8[8] = {a03.x, a03.y, a03.z, a03.w, a47.x, a47.y, a47.z, a47.w};
#pragma unroll
            for (int i = 0; i < 8; i++) {
                unsigned long long av;
                asm("mov.b64 %0, {%1,%2};" : "=l"(av) : "f"(ar8[i]), "f"(ar8[i]));
                asm("fma.rn.f32x2 %0, %1, %2, %0;" : "+l"(acc[i][0]) : "l"(av), "l"(w01));
                asm("fma.rn.f32x2 %0, %1, %2, %0;" : "+l"(acc[i][1]) : "l"(av), "l"(w23));
            }
        }
        __syncthreads();
    }

    int head = cg >> 4;
    int coff = cg & 15;
    float4 alv = *(const float4*)&al[head * ND + coff];
    float4 arv = *(const float4*)&ar[head * ND + coff];

#pragma unroll
    for (int i = 0; i < 8; i++) {
        int row = r0 + rg + i;
        float x0, x1, x2, x3;
        asm("mov.b64 {%0,%1}, %2;" : "=f"(x0), "=f"(x1) : "l"(acc[i][0]));
        asm("mov.b64 {%0,%1}, %2;" : "=f"(x2), "=f"(x3) : "l"(acc[i][1]));
        if (row < N_NODES)
            *(float4*)&g_feat[row * HD + cg] = make_float4(x0, x1, x2, x3);
        float elp = x0 * alv.x + x1 * alv.y + x2 * alv.z + x3 * alv.w;
        float erp = x0 * arv.x + x1 * arv.y + x2 * arv.z + x3 * arv.w;
        elp += __shfl_xor_sync(0xffffffffu, elp, 1);
        elp += __shfl_xor_sync(0xffffffffu, elp, 2);
        erp += __shfl_xor_sync(0xffffffffu, erp, 1);
        erp += __shfl_xor_sync(0xffffffffu, erp, 2);
        if ((lane & 3) == 0 && row < N_NODES) {
            g_el[row * NH + head] = elp;
            g_er[row * NH + head] = erp;
        }
    }
}

__device__ __forceinline__ float expleaky(float x) {
    x = (x > 0.f) ? x : NEG_SLOPE * x;
    return __expf(x);
}

// ---------------- CSR gather v2: 4 edges/iteration, all lanes active -------
// lane = (q = lane>>3: edge slot, hh = lane&7: head). Each iteration handles
// 4 edges: all 32 lanes compute exp(el+er) (4 edges x 8 heads), 4 independent
// feat LDG.128 per lane (MLP=4), weights broadcast via shuffles. Per-head
// denominators reduced once per node with butterfly shuffles.
#define GN 8
__global__ void __launch_bounds__(256) gat_gather(int li) {
    int lane = threadIdx.x & 31;
    int wid = (blockIdx.x * blockDim.x + threadIdx.x) >> 5;
    int n0 = wid * GN;
    if (n0 >= N_NODES) return;
    int q = lane >> 3;          // edge slot within a 4-edge group
    int hh = lane & 7;          // head for the exp path
    int h4 = lane >> 2;         // head owning channels lane*4..lane*4+3
    float4 bs = make_float4(0.f, 0.f, 0.f, 0.f);
    float4 bs2 = make_float4(0.f, 0.f, 0.f, 0.f);
    int nend = min(n0 + GN, N_NODES);

    for (int d = n0; d < nend; d++) {
        float er_hh = g_er[d * NH + hh];
        int beg = g_off[d], end = g_off[d + 1];
        float4 acc = make_float4(0.f, 0.f, 0.f, 0.f);
        float den = 0.f;
        for (int j = beg; j < end; j += 4) {
            int jq = j + q;
            bool valid = jq < end;
            int sq = g_esrc[valid ? jq : (end - 1)];
            float ee = valid ? expleaky(g_el[sq * NH + hh] + er_hh) : 0.f;
            den += ee;
            int s0 = __shfl_sync(0xffffffffu, sq, 0);
            int s1 = __shfl_sync(0xffffffffu, sq, 8);
            int s2 = __shfl_sync(0xffffffffu, sq, 16);
            int s3 = __shfl_sync(0xffffffffu, sq, 24);
            float4 f0 = ((const float4*)g_feat)[s0 * 32 + lane];
            float4 f1 = ((const float4*)g_feat)[s1 * 32 + lane];
            float4 f2 = ((const float4*)g_feat)[s2 * 32 + lane];
            float4 f3 = ((const float4*)g_feat)[s3 * 32 + lane];
            float m0 = __shfl_sync(0xffffffffu, ee, h4);
            float m1 = __shfl_sync(0xffffffffu, ee, 8 + h4);
            float m2 = __shfl_sync(0xffffffffu, ee, 16 + h4);
            float m3 = __shfl_sync(0xffffffffu, ee, 24 + h4);
            acc.x += m0 * f0.x + m1 * f1.x + m2 * f2.x + m3 * f3.x;
            acc.y += m0 * f0.y + m1 * f1.y + m2 * f2.y + m3 * f3.y;
            acc.z += m0 * f0.z + m1 * f1.z + m2 * f2.z + m3 * f3.z;
            acc.w += m0 * f0.w + m1 * f1.w + m2 * f2.w + m3 * f3.w;
        }
        // per-head denominator: sum over lanes with equal (lane&7)
        float dr = den;
        dr += __shfl_xor_sync(0xffffffffu, dr, 8);
        dr += __shfl_xor_sync(0xffffffffu, dr, 16);
        float myden = __shfl_sync(0xffffffffu, dr, h4);
        float inv = (myden != 0.f) ? 1.0f / myden : 0.f;
        acc.x *= inv; acc.y *= inv; acc.z *= inv; acc.w *= inv;
        ((float4*)g_agg)[d * 32 + lane] = acc;
        bs.x += acc.x; bs.y += acc.y; bs.z += acc.z; bs.w += acc.w;
        bs2.x += acc.x * acc.x; bs2.y += acc.y * acc.y;
        bs2.z += acc.z * acc.z; bs2.w += acc.w * acc.w;
    }
    red_add_v4(&g_bnsum[li * HD + lane * 4], bs);
    red_add_v4(&g_bnsum2[li * HD + lane * 4], bs2);
}

// Note: GAT bias b cancels inside BN (x - mean(x)), so it is never applied.
__global__ void bn_finalize(const float* __restrict__ gm, const float* __restrict__ be, int li) {
    int c = threadIdx.x;
    float inv_n = 1.0f / (float)N_NODES;
    float mu = g_bnsum[li * HD + c] * inv_n;
    float var = g_bnsum2[li * HD + c] * inv_n - mu * mu;
    float rs = rsqrtf(var + BN_EPS);
    float sc = rs * gm[c];
    g_scale[c] = sc;
    g_shift[c] = be[c] - mu * sc;
}

// ---------------- layer 1 epilogue fused with sum-pool ----------------
#define POOL_ROWS 512
__global__ void apply_bn_relu_res_pool(const int* __restrict__ gid) {
    int c = threadIdx.x;
    int r0 = blockIdx.x * POOL_ROWS;
    int r1 = min(r0 + POOL_ROWS, N_NODES);
    float sc = g_scale[c], sh = g_shift[c];
    float acc = 0.f;
    int cur = gid[r0];
    for (int r = r0; r < r1; r++) {
        int g = gid[r];
        float x = g_agg[r * HD + c] * sc + sh;
        x = fmaxf(x, 0.f) + g_h1[r * HD + c];
        if (g != cur) {
            atomicAdd(&g_pooled[cur * HD + c], acc);
            acc = 0.f;
            cur = g;
        }
        acc += x;
    }
    atomicAdd(&g_pooled[cur * HD + c], acc);
}

// ---------------- masked prediction head ----------------
__global__ void final_linear(const float* __restrict__ pW, const float* __restrict__ pb,
                             const float* __restrict__ mask, float* __restrict__ out) {
    __shared__ float p[HD];
    int g = blockIdx.x;
    int o = threadIdx.x;
    p[o] = g_pooled[g * HD + o];
    p[o + 64] = g_pooled[g * HD + o + 64];
    __syncthreads();
    float s = 0.f;
#pragma unroll 4
    for (int c = 0; c < HD; c++) {
        float w = pW[o * HD + c];
        float m = (mask[o * HD + c] > 0.5f) ? 1.f : 0.f;
        s += p[c] * w * m;
    }
    out[g * OUT_DIM + o] = s + pb[o];
}

// ---------------- launch ----------------
extern "C" void kernel_launch(void* const* d_in, const int* in_sizes, int n_in,
                              void* d_out, int out_size) {
    const float* h    = (const float*)d_in[0];
    const int*   src  = (const int*)d_in[1];
    const int*   dst  = (const int*)d_in[2];
    const int*   gid  = (const int*)d_in[3];
    const float* W0   = (const float*)d_in[4];
    const float* al0  = (const float*)d_in[5];
    const float* ar0  = (const float*)d_in[6];
    const float* g0   = (const float*)d_in[8];
    const float* be0  = (const float*)d_in[9];
    const float* W1   = (const float*)d_in[10];
    const float* al1  = (const float*)d_in[11];
    const float* ar1  = (const float*)d_in[12];
    const float* g1   = (const float*)d_in[14];
    const float* be1  = (const float*)d_in[15];
    const float* pW   = (const float*)d_in[16];
    const float* pb   = (const float*)d_in[17];
    const float* mask = (const float*)d_in[18];
    float* out = (float*)d_out;

    static cudaStream_t s_side = nullptr;
    static cudaEvent_t e_fork = nullptr, e_join = nullptr;
    if (s_side == nullptr) {
        cudaStreamCreateWithFlags(&s_side, cudaStreamNonBlocking);
        cudaEventCreateWithFlags(&e_fork, cudaEventDisableTiming);
        cudaEventCreateWithFlags(&e_join, cudaEventDisableTiming);
    }

    const int ggrid  = (N_NODES + 63) / 64;                  // 1563
    const int egrid  = (N_EDGES + 255) / 256;                // 6250
    const int zgrid  = (N_NODES / 4 + 255) / 256;            // 98
    const int gagrid = (N_NODES / (8 * GN)) + 1;             // 1563
    const int pgrid  = (N_NODES + POOL_ROWS - 1) / POOL_ROWS;// 196

    // ---- fork: CSR build + zeroing on side stream, overlapped with gemm0 ----
    cudaEventRecord(e_fork, 0);
    cudaStreamWaitEvent(s_side, e_fork, 0);
    zero_all<<<zgrid, 256, 0, s_side>>>();
    csr_hist<<<egrid, 256, 0, s_side>>>(dst);
    csr_scan1<<<SCAN_NBLK, SCAN_B, 0, s_side>>>();
    csr_scan2<<<1, 256, 0, s_side>>>();
    csr_scan3<<<SCAN_NBLK, SCAN_B, 0, s_side>>>();
    csr_scatter<<<egrid, 256, 0, s_side>>>(src, dst);
    cudaEventRecord(e_join, s_side);

    // ---- layer 0 (gemm0 runs concurrently with CSR build) ----
    gemm128<<<ggrid, 256>>>(h, W0, al0, ar0, 0);
    cudaStreamWaitEvent(0, e_join, 0);
    gat_gather<<<gagrid, 256>>>(0);
    bn_finalize<<<1, 128>>>(g0, be0, 0);

    // ---- layer 1 (bn+relu of layer 0 fused into gemm1's A loader) ----
    gemm128<<<ggrid, 256>>>(nullptr, W1, al1, ar1, 1);
    gat_gather<<<gagrid, 256>>>(1);
    bn_finalize<<<1, 128>>>(g1, be1, 1);
    apply_bn_relu_res_pool<<<pgrid, 128>>>(gid);

    // ---- head ----
    final_linear<<<G_GRAPHS, OUT_DIM>>>(pW, pb, mask, out);
}